// round 4
// baseline (speedup 1.0000x reference)
#include <cuda_runtime.h>
#include <math.h>
#include <stdint.h>

#define NATC 1024
#define DEGC 32
#define DC   128
#define RC   64
#define LC   3
#define BC   16
#define EC   (NATC*DEGC)      /* 32768 */
#define HDC  (DC/2)           /* 64 */
#define BNAT (BC*NATC)        /* 16384 */
#define BE   ((size_t)BC*EC)  /* 524288 */
#define M4   (4*BNAT)         /* 65536 */
#define NQ   4096
#define QB   16
#define DMAXF 20.0f
#define LOG2C 0.69314718055994530942f

// ---------------- scratch (allocation-free: __device__ globals) ----------------
__device__ float g_feat4[(size_t)4*BNAT*DC];
__device__ float g_xw4 [(size_t)4*BNAT*DC];
__device__ float g_y4  [(size_t)4*BNAT*DC];
__device__ float g_t34 [(size_t)4*BNAT*DC];
__device__ float g_h4  [(size_t)4*BNAT*HDC];
__device__ float g_d   [BE];
__device__ float g_ddot[(size_t)BE*3];
__device__ float2 g_tab[(size_t)NQ*DC];   // per-layer (rebuilt): (f(d), f'(d)) per dim
__device__ int   g_sflag[EC];

// ---------------- math helpers ----------------
__device__ __forceinline__ float sspf(float x) {
    return fmaxf(x, 0.f) + log1pf(expf(-fabsf(x))) - LOG2C;
}
__device__ __forceinline__ float sigf(float x) {
    return 1.f / (1.f + expf(-x));
}

// ---------------- prep ----------------
__global__ void prepBuildK(const int* __restrict__ idx_i, const int* __restrict__ idx_j) {
    int e = blockIdx.x * blockDim.x + threadIdx.x;
    if (e >= EC) return;
    g_sflag[e] = (idx_i[e] == 0 || idx_j[e] == 0) ? 1 : 0;
}

__global__ void initK(const float* __restrict__ emb, const int* __restrict__ types) {
    int gid = blockIdx.x * blockDim.x + threadIdx.x;      // over BNAT*DC
    if (gid >= BNAT * DC) return;
    int bn = gid / DC;
    int d  = gid - bn * DC;
    int ty = types[bn];
    const size_t TB = (size_t)BNAT * DC;
    g_feat4[gid]        = emb[(size_t)ty * DC + d];
    g_feat4[TB + gid]   = 0.f;
    g_feat4[2*TB + gid] = 0.f;
    g_feat4[3*TB + gid] = 0.f;
}

__global__ void distK(const float* __restrict__ pos,
                      const int* __restrict__ idx_i, const int* __restrict__ idx_j) {
    int gid = blockIdx.x * blockDim.x + threadIdx.x;      // over B*E
    if (gid >= (int)BE) return;
    int b = gid / EC, e = gid - b * EC;
    int i = idx_i[e], j = idx_j[e];
    const float* pi = pos + ((size_t)b * NATC + i) * 3;
    const float* pj = pos + ((size_t)b * NATC + j) * 3;
    float dx = pi[0]-pj[0], dy = pi[1]-pj[1], dz = pi[2]-pj[2];
    float dv = sqrtf(dx*dx + dy*dy + dz*dz + 1e-8f);
    g_d[gid] = dv;
    float c = (float)((i == 0) - (j == 0));
    float inv = c / dv;
    g_ddot[(size_t)gid*3 + 0] = dx * inv;
    g_ddot[(size_t)gid*3 + 1] = dy * inv;
    g_ddot[(size_t)gid*3 + 2] = dz * inv;
}

// ------ per-layer edge-MLP lookup table (weights cached in dynamic smem) ------
__global__ void tabK2(const float* __restrict__ Wf1, const float* __restrict__ bf1,
                      const float* __restrict__ Wf2, const float* __restrict__ bf2,
                      const float* __restrict__ centers, const float* __restrict__ gammaA, int l) {
    extern __shared__ float sw[];                 // [RC*DC] Wf1 + [DC*DC] Wf2
    float* w1s = sw;
    float* w2s = sw + RC*DC;
    __shared__ float rbf[RC], drb[RC], s1[DC], ds1[DC];
    int t = threadIdx.x;   // 0..127
    for (int idx = t; idx < RC*DC; idx += DC) w1s[idx] = Wf1[(size_t)l*RC*DC + idx];
    for (int idx = t; idx < DC*DC; idx += DC) w2s[idx] = Wf2[(size_t)l*DC*DC + idx];
    float b1v = bf1[l*DC + t];
    float b2v = bf2[l*DC + t];
    float gm = 0.f, cc = 0.f;
    if (t < RC) { gm = gammaA[l*RC + t]; cc = centers[l*RC + t]; }
    __syncthreads();

    for (int qi = 0; qi < QB; qi++) {
        int q = blockIdx.x * QB + qi;
        float dq = q * (DMAXF / (float)(NQ - 1));
        if (t < RC) {
            float diff = dq - cc;
            float r = expf(-gm * diff * diff);
            rbf[t] = r;
            drb[t] = -2.f * gm * diff * r;
        }
        __syncthreads();
        float t1 = b1v, dt1 = 0.f;
        #pragma unroll 8
        for (int r = 0; r < RC; r++) {
            float w = w1s[r * DC + t];
            t1  += rbf[r] * w;
            dt1 += drb[r] * w;
        }
        s1[t]  = sspf(t1);
        ds1[t] = sigf(t1) * dt1;
        __syncthreads();
        float t2 = b2v, dt2 = 0.f;
        #pragma unroll 8
        for (int k = 0; k < DC; k++) {
            float w = w2s[k * DC + t];
            t2  += s1[k] * w;
            dt2 += ds1[k] * w;
        }
        g_tab[(size_t)q*DC + t] = make_float2(sspf(t2), sigf(t2) * dt2);
        __syncthreads();
    }
}

// ------- SGEMM: C[M,N] = A[M,K] @ B[K,N] (+bias rows<biasRows)(+res), double-buffered -------
__global__ void __launch_bounds__(256) sgemmK(
    const float* __restrict__ A, const float* __restrict__ Bm, float* __restrict__ C,
    int M, int N, int K, const float* __restrict__ bias, int biasRows,
    const float* __restrict__ res)
{
    __shared__ float As[2][8][132];
    __shared__ float Bs[2][8][128];
    const int tid = threadIdx.x;
    const int m0 = blockIdx.x * 128;
    const int n0 = blockIdx.y * 128;
    const int tx = tid & 15, ty = tid >> 4;
    const int aRow = tid >> 1, aCol = (tid & 1) << 2;
    const int bRow = tid >> 5, bCol = (tid & 31) << 2;
    const float* Ap = A + (size_t)(m0 + aRow) * K + aCol;
    const bool bValid = (n0 + bCol) < N;
    const float* Bp = Bm + (size_t)bRow * N + (n0 + bCol);

    float4 av = *reinterpret_cast<const float4*>(Ap);
    float4 bv = bValid ? *reinterpret_cast<const float4*>(Bp) : make_float4(0.f,0.f,0.f,0.f);
    As[0][aCol+0][aRow] = av.x; As[0][aCol+1][aRow] = av.y;
    As[0][aCol+2][aRow] = av.z; As[0][aCol+3][aRow] = av.w;
    *reinterpret_cast<float4*>(&Bs[0][bRow][bCol]) = bv;
    __syncthreads();

    float acc[8][8];
    #pragma unroll
    for (int i = 0; i < 8; i++)
        #pragma unroll
        for (int j = 0; j < 8; j++) acc[i][j] = 0.f;

    const int nT = K >> 3;
    for (int tIt = 0; tIt < nT; tIt++) {
        const int cur = tIt & 1, nxt = cur ^ 1;
        float4 aN, bN;
        const bool more = (tIt + 1 < nT);
        if (more) {
            aN = *reinterpret_cast<const float4*>(Ap + (tIt + 1) * 8);
            bN = bValid ? *reinterpret_cast<const float4*>(Bp + (size_t)(tIt + 1) * 8 * N)
                        : make_float4(0.f,0.f,0.f,0.f);
        }
        #pragma unroll
        for (int k = 0; k < 8; k++) {
            float a[8], b[8];
            *reinterpret_cast<float4*>(a)     = *reinterpret_cast<const float4*>(&As[cur][k][ty*8]);
            *reinterpret_cast<float4*>(a + 4) = *reinterpret_cast<const float4*>(&As[cur][k][ty*8 + 4]);
            *reinterpret_cast<float4*>(b)     = *reinterpret_cast<const float4*>(&Bs[cur][k][tx*8]);
            *reinterpret_cast<float4*>(b + 4) = *reinterpret_cast<const float4*>(&Bs[cur][k][tx*8 + 4]);
            #pragma unroll
            for (int i = 0; i < 8; i++)
                #pragma unroll
                for (int j = 0; j < 8; j++)
                    acc[i][j] += a[i] * b[j];
        }
        if (more) {
            As[nxt][aCol+0][aRow] = aN.x; As[nxt][aCol+1][aRow] = aN.y;
            As[nxt][aCol+2][aRow] = aN.z; As[nxt][aCol+3][aRow] = aN.w;
            *reinterpret_cast<float4*>(&Bs[nxt][bRow][bCol]) = bN;
            __syncthreads();
        }
    }

    #pragma unroll
    for (int i = 0; i < 8; i++) {
        int row = m0 + ty*8 + i;
        bool useB = (bias != nullptr) && (row < biasRows);
        #pragma unroll
        for (int j = 0; j < 8; j++) {
            int col = n0 + tx*8 + j;
            if (col < N) {
                float v = acc[i][j];
                if (useB) v += bias[col];
                if (res) v += res[(size_t)row * N + col];
                C[(size_t)row * N + col] = v;
            }
        }
    }
}

// ---------------- fused interp(f) * gather(x) + segment sum (primal + 3 tangents) -------------
__global__ void __launch_bounds__(128) aggK(const int* __restrict__ idx_j) {
    int i = blockIdx.x, b = blockIdx.y, t = threadIdx.x;   // t = 0..127
    const size_t TB = (size_t)BNAT * DC;
    const float invh = (float)(NQ - 1) / DMAXF;
    const float hh   = DMAXF / (float)(NQ - 1);

    __shared__ float sd[DEGC];
    __shared__ int   sj[DEGC];
    __shared__ int   sf[DEGC];
    __shared__ float sdx[DEGC], sdy[DEGC], sdz[DEGC];
    if (t < DEGC) {
        int e = i * DEGC + t;
        sd[t] = g_d[(size_t)b*EC + e];
        sj[t] = idx_j[e];
        sf[t] = g_sflag[e];
        size_t db = ((size_t)b*EC + e) * 3;
        sdx[t] = g_ddot[db + 0];
        sdy[t] = g_ddot[db + 1];
        sdz[t] = g_ddot[db + 2];
    }
    __syncthreads();

    float y = 0.f, y0 = 0.f, y1 = 0.f, y2 = 0.f;
    #pragma unroll 4
    for (int eo = 0; eo < DEGC; eo++) {
        float dv = sd[eo];
        float u = fminf(dv * invh, (float)(NQ - 1));
        int q = (int)u;
        if (q > NQ - 2) q = NQ - 2;
        float w = u - (float)q;
        float2 a0 = g_tab[(size_t)q * DC + t];
        float2 a1 = g_tab[(size_t)(q + 1) * DC + t];
        float w2 = w * w, w3 = w2 * w;
        float h00 = 2.f*w3 - 3.f*w2 + 1.f;
        float h01 = 1.f - h00;
        float h10 = w3 - 2.f*w2 + w;
        float h11 = w3 - w2;
        float fv = h00 * a0.x + h01 * a1.x + hh * (h10 * a0.y + h11 * a1.y);

        int j = sj[eo];
        size_t xb = ((size_t)b*NATC + j)*DC + t;
        float xv = g_xw4[xb];
        y  += xv * fv;
        y0 += g_xw4[TB   + xb] * fv;
        y1 += g_xw4[2*TB + xb] * fv;
        y2 += g_xw4[3*TB + xb] * fv;

        if (sf[eo]) {
            float dcom = 6.f * (w2 - w);
            float F = dcom * (a0.x - a1.x) * invh
                    + (3.f*w2 - 4.f*w + 1.f) * a0.y
                    + (3.f*w2 - 2.f*w) * a1.y;
            float xF = xv * F;
            y0 += sdx[eo] * xF;
            y1 += sdy[eo] * xF;
            y2 += sdz[eo] * xF;
        }
    }
    size_t yb = ((size_t)b*NATC + i)*DC + t;
    g_y4[yb] = y; g_y4[TB+yb] = y0; g_y4[2*TB+yb] = y1; g_y4[3*TB+yb] = y2;
}

// ---- layer-0 variant: tangent features are all zero, so only special-edge tangent terms ----
__global__ void __launch_bounds__(128) aggLightK(const int* __restrict__ idx_j) {
    int i = blockIdx.x, b = blockIdx.y, t = threadIdx.x;
    const size_t TB = (size_t)BNAT * DC;
    const float invh = (float)(NQ - 1) / DMAXF;
    const float hh   = DMAXF / (float)(NQ - 1);

    __shared__ float sd[DEGC];
    __shared__ int   sj[DEGC];
    __shared__ int   sf[DEGC];
    __shared__ float sdx[DEGC], sdy[DEGC], sdz[DEGC];
    if (t < DEGC) {
        int e = i * DEGC + t;
        sd[t] = g_d[(size_t)b*EC + e];
        sj[t] = idx_j[e];
        sf[t] = g_sflag[e];
        size_t db = ((size_t)b*EC + e) * 3;
        sdx[t] = g_ddot[db + 0];
        sdy[t] = g_ddot[db + 1];
        sdz[t] = g_ddot[db + 2];
    }
    __syncthreads();

    float y = 0.f, y0 = 0.f, y1 = 0.f, y2 = 0.f;
    #pragma unroll 4
    for (int eo = 0; eo < DEGC; eo++) {
        float dv = sd[eo];
        float u = fminf(dv * invh, (float)(NQ - 1));
        int q = (int)u;
        if (q > NQ - 2) q = NQ - 2;
        float w = u - (float)q;
        float2 a0 = g_tab[(size_t)q * DC + t];
        float2 a1 = g_tab[(size_t)(q + 1) * DC + t];
        float w2 = w * w, w3 = w2 * w;
        float h00 = 2.f*w3 - 3.f*w2 + 1.f;
        float h01 = 1.f - h00;
        float h10 = w3 - 2.f*w2 + w;
        float h11 = w3 - w2;
        float fv = h00 * a0.x + h01 * a1.x + hh * (h10 * a0.y + h11 * a1.y);

        int j = sj[eo];
        size_t xb = ((size_t)b*NATC + j)*DC + t;
        float xv = g_xw4[xb];
        y += xv * fv;

        if (sf[eo]) {
            float dcom = 6.f * (w2 - w);
            float F = dcom * (a0.x - a1.x) * invh
                    + (3.f*w2 - 4.f*w + 1.f) * a0.y
                    + (3.f*w2 - 2.f*w) * a1.y;
            float xF = xv * F;
            y0 += sdx[eo] * xF;
            y1 += sdy[eo] * xF;
            y2 += sdz[eo] * xF;
        }
    }
    size_t yb = ((size_t)b*NATC + i)*DC + t;
    g_y4[yb] = y; g_y4[TB+yb] = y0; g_y4[2*TB+yb] = y1; g_y4[3*TB+yb] = y2;
}

// ---------------- ssp on primal rows, sigmoid-mask on tangent rows (after Y4@W2) -------------
__global__ void sspTangentK() {
    int idx = blockIdx.x * blockDim.x + threadIdx.x;   // over BNAT*DC
    if (idx >= BNAT * DC) return;
    const size_t TB = (size_t)BNAT * DC;
    float p = g_t34[idx];
    float sg = sigf(p);
    g_t34[idx] = sspf(p);
    g_t34[TB + idx]   *= sg;
    g_t34[2*TB + idx] *= sg;
    g_t34[3*TB + idx] *= sg;
}

// ---------------- final energy tangent reduction ----------------
__global__ void energyK(const float* __restrict__ We, float* __restrict__ out) {
    int b = blockIdx.x, tid = threadIdx.x;
    const size_t TH = (size_t)BNAT * HDC;
    float a0 = 0.f, a1 = 0.f, a2 = 0.f;
    for (int idx = tid; idx < NATC * HDC; idx += 256) {
        int k = idx & (HDC - 1);
        size_t base = (size_t)b * NATC * HDC + idx;
        float p = g_h4[base];
        float w = We[k] * sigf(p);
        a0 += w * g_h4[TH   + base];
        a1 += w * g_h4[2*TH + base];
        a2 += w * g_h4[3*TH + base];
    }
    __shared__ float r0[256], r1[256], r2[256];
    r0[tid] = a0; r1[tid] = a1; r2[tid] = a2;
    __syncthreads();
    for (int s = 128; s > 0; s >>= 1) {
        if (tid < s) { r0[tid] += r0[tid+s]; r1[tid] += r1[tid+s]; r2[tid] += r2[tid+s]; }
        __syncthreads();
    }
    if (tid == 0) {
        out[b*3 + 0] = -r0[0];
        out[b*3 + 1] = -r1[0];
        out[b*3 + 2] = -r2[0];
    }
}

// ---------------- host ----------------
extern "C" void kernel_launch(void* const* d_in, const int* in_sizes, int n_in,
                              void* d_out, int out_size) {
    const float* pos     = (const float*)d_in[0];
    const int*   types   = (const int*)  d_in[1];
    const int*   idx_i   = (const int*)  d_in[2];
    const int*   idx_j   = (const int*)  d_in[3];
    /* d_in[4] = seg_i (== idx_i, unused) */
    const float* emb     = (const float*)d_in[5];
    const float* W1      = (const float*)d_in[6];
    const float* b1      = (const float*)d_in[7];
    const float* Wf1     = (const float*)d_in[8];
    const float* bf1     = (const float*)d_in[9];
    const float* Wf2     = (const float*)d_in[10];
    const float* bf2     = (const float*)d_in[11];
    const float* W2      = (const float*)d_in[12];
    const float* b2      = (const float*)d_in[13];
    const float* W3      = (const float*)d_in[14];
    const float* b3      = (const float*)d_in[15];
    const float* centers = (const float*)d_in[16];
    const float* gammaA  = (const float*)d_in[17];
    const float* Wd      = (const float*)d_in[18];
    const float* bd      = (const float*)d_in[19];
    const float* We      = (const float*)d_in[20];
    float* out = (float*)d_out;

    float *feat4, *xw4, *y4, *t34, *h4;
    cudaGetSymbolAddress((void**)&feat4, g_feat4);
    cudaGetSymbolAddress((void**)&xw4,  g_xw4);
    cudaGetSymbolAddress((void**)&y4,   g_y4);
    cudaGetSymbolAddress((void**)&t34,  g_t34);
    cudaGetSymbolAddress((void**)&h4,   g_h4);

    static int tabAttrDone = 0;
    const int tabSmem = (RC*DC + DC*DC) * sizeof(float);   // 96 KB
    if (!tabAttrDone) {
        cudaFuncSetAttribute(tabK2, cudaFuncAttributeMaxDynamicSharedMemorySize, tabSmem);
        tabAttrDone = 1;
    }

    prepBuildK<<<EC/256, 256>>>(idx_i, idx_j);
    initK<<<(BNAT*DC)/256, 256>>>(emb, types);
    distK<<<(int)(BE/256), 256>>>(pos, idx_i, idx_j);

    for (int l = 0; l < LC; l++) {
        // x = feat @ W1 + b1 (tangents: featdot @ W1; all-zero at l==0 -> primal only)
        int mW1 = (l == 0) ? BNAT : M4;
        sgemmK<<<dim3(mW1/128, 1), 256>>>(feat4, W1 + (size_t)l*DC*DC, xw4,
                                          mW1, DC, DC, b1 + l*DC, BNAT, nullptr);
        // edge-MLP lookup table (value + derivative) for this layer
        tabK2<<<NQ/QB, DC, tabSmem>>>(Wf1, bf1, Wf2, bf2, centers, gammaA, l);
        // y = segsum(x[j]*f); ydot = segsum(xdot[j]*f + ddot*x[j]*F)
        if (l == 0) aggLightK<<<dim3(NATC, BC), 128>>>(idx_j);
        else        aggK<<<dim3(NATC, BC), 128>>>(idx_j);
        // t3 = y @ W2 + b2 (tangents raw)
        sgemmK<<<dim3(M4/128, 1), 256>>>(y4, W2 + (size_t)l*DC*DC, t34,
                                         M4, DC, DC, b2 + l*DC, BNAT, nullptr);
        // primal -> ssp(t3); tangents *= sigmoid(t3)
        sspTangentK<<<(BNAT*DC)/256, 256>>>();
        // feat += s3 @ W3 + b3 (tangents: featdot += s3dot @ W3)
        sgemmK<<<dim3(M4/128, 1), 256>>>(t34, W3 + (size_t)l*DC*DC, feat4,
                                         M4, DC, DC, b3 + l*DC, BNAT, feat4);
    }
    // pre = feat @ Wd + bd (raw); tangents: featdot @ Wd
    sgemmK<<<dim3(M4/128, 1), 256>>>(feat4, Wd, h4, M4, HDC, DC, bd, BNAT, nullptr);
    // out[b,0,t] = -sum We[k]*sigmoid(pre)*predot_t
    energyK<<<BC, 256>>>(We, out);
}

// round 6
// speedup vs baseline: 1.3529x; 1.3529x over previous
#include <cuda_runtime.h>
#include <cuda_bf16.h>
#include <math.h>
#include <stdint.h>

#define NATC 1024
#define DEGC 32
#define DC   128
#define RC   64
#define LC   3
#define BC   16
#define EC   (NATC*DEGC)      /* 32768 */
#define HDC  (DC/2)           /* 64 */
#define BNAT (BC*1024)        /* 16384 */
#define BE   ((size_t)BC*EC)  /* 524288 */
#define M4   (4*BNAT)         /* 65536 */
#define NQ   4096
#define QB   16
#define DMAXF 20.0f
#define LOG2C 0.69314718055994530942f

// ---------------- scratch (allocation-free: __device__ globals) ----------------
__device__ float g_feat4[(size_t)4*BNAT*DC];
__device__ float g_xw4 [(size_t)4*BNAT*DC];
__device__ float g_y4  [(size_t)4*BNAT*DC];
__device__ float g_t34 [(size_t)4*BNAT*DC];
__device__ float g_h4  [(size_t)4*BNAT*HDC];
__device__ float g_d   [BE];
__device__ float g_ddot[(size_t)BE*3];
__device__ float2 g_tab[(size_t)NQ*DC];
__device__ int   g_sflag[EC];

// ---------------- math helpers ----------------
__device__ __forceinline__ float sspf(float x) {
    return fmaxf(x, 0.f) + log1pf(expf(-fabsf(x))) - LOG2C;
}
__device__ __forceinline__ float sigf(float x) {
    return 1.f / (1.f + expf(-x));
}

// ---------------- prep ----------------
__global__ void prepBuildK(const int* __restrict__ idx_i, const int* __restrict__ idx_j) {
    int e = blockIdx.x * blockDim.x + threadIdx.x;
    if (e >= EC) return;
    g_sflag[e] = (idx_i[e] == 0 || idx_j[e] == 0) ? 1 : 0;
}

__global__ void initK(const float* __restrict__ emb, const int* __restrict__ types) {
    int gid = blockIdx.x * blockDim.x + threadIdx.x;
    if (gid >= BNAT * DC) return;
    int bn = gid / DC;
    int d  = gid - bn * DC;
    int ty = types[bn];
    const size_t TB = (size_t)BNAT * DC;
    g_feat4[gid]        = emb[(size_t)ty * DC + d];
    g_feat4[TB + gid]   = 0.f;
    g_feat4[2*TB + gid] = 0.f;
    g_feat4[3*TB + gid] = 0.f;
}

__global__ void distK(const float* __restrict__ pos,
                      const int* __restrict__ idx_i, const int* __restrict__ idx_j) {
    int gid = blockIdx.x * blockDim.x + threadIdx.x;
    if (gid >= (int)BE) return;
    int b = gid / EC, e = gid - b * EC;
    int i = idx_i[e], j = idx_j[e];
    const float* pi = pos + ((size_t)b * NATC + i) * 3;
    const float* pj = pos + ((size_t)b * NATC + j) * 3;
    float dx = pi[0]-pj[0], dy = pi[1]-pj[1], dz = pi[2]-pj[2];
    float dv = sqrtf(dx*dx + dy*dy + dz*dz + 1e-8f);
    g_d[gid] = dv;
    float c = (float)((i == 0) - (j == 0));
    float inv = c / dv;
    g_ddot[(size_t)gid*3 + 0] = dx * inv;
    g_ddot[(size_t)gid*3 + 1] = dy * inv;
    g_ddot[(size_t)gid*3 + 2] = dz * inv;
}

// ------ per-layer edge-MLP lookup table (weights cached in dynamic smem) ------
__global__ void tabK2(const float* __restrict__ Wf1, const float* __restrict__ bf1,
                      const float* __restrict__ Wf2, const float* __restrict__ bf2,
                      const float* __restrict__ centers, const float* __restrict__ gammaA, int l) {
    extern __shared__ float sw[];
    float* w1s = sw;
    float* w2s = sw + RC*DC;
    __shared__ float rbf[RC], drb[RC], s1[DC], ds1[DC];
    int t = threadIdx.x;
    for (int idx = t; idx < RC*DC; idx += DC) w1s[idx] = Wf1[(size_t)l*RC*DC + idx];
    for (int idx = t; idx < DC*DC; idx += DC) w2s[idx] = Wf2[(size_t)l*DC*DC + idx];
    float b1v = bf1[l*DC + t];
    float b2v = bf2[l*DC + t];
    float gm = 0.f, cc = 0.f;
    if (t < RC) { gm = gammaA[l*RC + t]; cc = centers[l*RC + t]; }
    __syncthreads();

    for (int qi = 0; qi < QB; qi++) {
        int q = blockIdx.x * QB + qi;
        float dq = q * (DMAXF / (float)(NQ - 1));
        if (t < RC) {
            float diff = dq - cc;
            float r = expf(-gm * diff * diff);
            rbf[t] = r;
            drb[t] = -2.f * gm * diff * r;
        }
        __syncthreads();
        float t1 = b1v, dt1 = 0.f;
        #pragma unroll 8
        for (int r = 0; r < RC; r++) {
            float w = w1s[r * DC + t];
            t1  += rbf[r] * w;
            dt1 += drb[r] * w;
        }
        s1[t]  = sspf(t1);
        ds1[t] = sigf(t1) * dt1;
        __syncthreads();
        float t2 = b2v, dt2 = 0.f;
        #pragma unroll 8
        for (int k = 0; k < DC; k++) {
            float w = w2s[k * DC + t];
            t2  += s1[k] * w;
            dt2 += ds1[k] * w;
        }
        g_tab[(size_t)q*DC + t] = make_float2(sspf(t2), sigf(t2) * dt2);
        __syncthreads();
    }
}

// ---------------- mma.sync bf16 GEMM: C[M,128] = A[M,128] @ W[128,128] (+bias)(+res) -------
// hi/lo split: A@W ~= Ah@Wh + Al@Wh + Ah@Wl (error ~2^-16)
#define PADK 136
#define PLANEB (128 * PADK * 2)          /* bytes per bf16 plane */
#define MMA_SMEM (4 * PLANEB)            /* Ah, Al, Bh(t), Bl(t) */

__device__ __forceinline__ void mma16816(float* c, uint32_t a0, uint32_t a1, uint32_t a2, uint32_t a3,
                                         uint32_t b0, uint32_t b1) {
    asm volatile(
        "mma.sync.aligned.m16n8k16.row.col.f32.bf16.bf16.f32 "
        "{%0,%1,%2,%3}, {%4,%5,%6,%7}, {%8,%9}, {%0,%1,%2,%3};"
        : "+f"(c[0]), "+f"(c[1]), "+f"(c[2]), "+f"(c[3])
        : "r"(a0), "r"(a1), "r"(a2), "r"(a3), "r"(b0), "r"(b1));
}

__device__ __forceinline__ uint32_t pack_hi(float x0, float x1) {
    __nv_bfloat162 v; v.x = __float2bfloat16(x0); v.y = __float2bfloat16(x1);
    return *reinterpret_cast<uint32_t*>(&v);
}
__device__ __forceinline__ uint32_t pack_lo(float x0, float x1) {
    __nv_bfloat16 h0 = __float2bfloat16(x0), h1 = __float2bfloat16(x1);
    __nv_bfloat162 v;
    v.x = __float2bfloat16(x0 - __bfloat162float(h0));
    v.y = __float2bfloat16(x1 - __bfloat162float(h1));
    return *reinterpret_cast<uint32_t*>(&v);
}

__global__ void __launch_bounds__(256) mmaGemmK(
    const float* __restrict__ A, const float* __restrict__ W, float* __restrict__ C,
    int M, const float* __restrict__ bias, int biasRows, const float* __restrict__ res)
{
    extern __shared__ char sm[];
    uint16_t* Ah = reinterpret_cast<uint16_t*>(sm);
    uint16_t* Al = reinterpret_cast<uint16_t*>(sm + PLANEB);
    uint16_t* Bh = reinterpret_cast<uint16_t*>(sm + 2*PLANEB);   // transposed: [n][k]
    uint16_t* Bl = reinterpret_cast<uint16_t*>(sm + 3*PLANEB);

    const int tid = threadIdx.x;
    const int m0 = blockIdx.x * 128;

    // ---- load + split A (coalesced; STS conflict-free) ----
    {
        const float* Ab = A + (size_t)m0 * DC;
        #pragma unroll 8
        for (int it = 0; it < 32; it++) {
            int idx = it * 256 + tid;          // over 8192 float2
            int row = idx >> 6;
            int c2  = idx & 63;
            float2 x = *reinterpret_cast<const float2*>(Ab + (size_t)row * DC + c2 * 2);
            uint32_t off = row * PADK + c2 * 2;
            *reinterpret_cast<uint32_t*>(Ah + off) = pack_hi(x.x, x.y);
            *reinterpret_cast<uint32_t*>(Al + off) = pack_lo(x.x, x.y);
        }
    }
    // ---- load + split W transposed: Bt[n][k] = W[k][n] ----
    {
        int n = tid & 127;
        int kp0 = tid >> 7;                    // 0 or 1
        for (int kp = kp0; kp < 64; kp += 2) {
            float x0 = W[(size_t)(2*kp)     * DC + n];
            float x1 = W[(size_t)(2*kp + 1) * DC + n];
            uint32_t off = n * PADK + kp * 2;
            *reinterpret_cast<uint32_t*>(Bh + off) = pack_hi(x0, x1);
            *reinterpret_cast<uint32_t*>(Bl + off) = pack_lo(x0, x1);
        }
    }
    __syncthreads();

    const int wid = tid >> 5, lane = tid & 31;
    const int wm = wid & 3, wn = wid >> 2;     // 4 m-quadrants x 2 n-halves
    const int lr = lane >> 2, lc = lane & 3;

    float acc[2][8][4];
    #pragma unroll
    for (int mt = 0; mt < 2; mt++)
        #pragma unroll
        for (int nt = 0; nt < 8; nt++)
            #pragma unroll
            for (int q = 0; q < 4; q++) acc[mt][nt][q] = 0.f;

    const int arow0 = wm * 32 + lr;            // + mt*16 (+8 for a1/a3)
    const int bn0   = wn * 64 + lr;            // + nt*8

    #pragma unroll
    for (int pass = 0; pass < 3; pass++) {
        const uint16_t* Ap = (pass == 1) ? Al : Ah;
        const uint16_t* Bp = (pass == 2) ? Bl : Bh;
        #pragma unroll
        for (int ks = 0; ks < 8; ks++) {
            const int k0 = ks * 16 + lc * 2;
            uint32_t af[2][4];
            #pragma unroll
            for (int mt = 0; mt < 2; mt++) {
                const uint16_t* base = Ap + (arow0 + mt*16) * PADK + k0;
                af[mt][0] = *reinterpret_cast<const uint32_t*>(base);
                af[mt][1] = *reinterpret_cast<const uint32_t*>(base + 8 * PADK);
                af[mt][2] = *reinterpret_cast<const uint32_t*>(base + 8);
                af[mt][3] = *reinterpret_cast<const uint32_t*>(base + 8 * PADK + 8);
            }
            #pragma unroll
            for (int nt = 0; nt < 8; nt++) {
                const uint16_t* bb = Bp + (bn0 + nt*8) * PADK + k0;
                uint32_t b0 = *reinterpret_cast<const uint32_t*>(bb);
                uint32_t b1 = *reinterpret_cast<const uint32_t*>(bb + 8);
                mma16816(acc[0][nt], af[0][0], af[0][1], af[0][2], af[0][3], b0, b1);
                mma16816(acc[1][nt], af[1][0], af[1][1], af[1][2], af[1][3], b0, b1);
            }
        }
    }

    // ---- epilogue: fused bias (rows < biasRows) + residual ----
    #pragma unroll
    for (int mt = 0; mt < 2; mt++) {
        int r0 = m0 + arow0 + mt * 16;
        int r1 = r0 + 8;
        bool ub0 = (bias != nullptr) && (r0 < biasRows);
        bool ub1 = (bias != nullptr) && (r1 < biasRows);
        #pragma unroll
        for (int nt = 0; nt < 8; nt++) {
            int col = wn * 64 + nt * 8 + lc * 2;
            float2 v0 = make_float2(acc[mt][nt][0], acc[mt][nt][1]);
            float2 v1 = make_float2(acc[mt][nt][2], acc[mt][nt][3]);
            if (ub0) { v0.x += bias[col]; v0.y += bias[col+1]; }
            if (ub1) { v1.x += bias[col]; v1.y += bias[col+1]; }
            if (res) {
                float2 r0v = *reinterpret_cast<const float2*>(res + (size_t)r0 * DC + col);
                float2 r1v = *reinterpret_cast<const float2*>(res + (size_t)r1 * DC + col);
                v0.x += r0v.x; v0.y += r0v.y;
                v1.x += r1v.x; v1.y += r1v.y;
            }
            *reinterpret_cast<float2*>(C + (size_t)r0 * DC + col) = v0;
            *reinterpret_cast<float2*>(C + (size_t)r1 * DC + col) = v1;
        }
    }
}

// ------- fp32 SGEMM (for Wd, N=64): C[M,N] = A[M,K]@B[K,N] (+bias rows<biasRows) -------
__global__ void __launch_bounds__(256) sgemmK(
    const float* __restrict__ A, const float* __restrict__ Bm, float* __restrict__ C,
    int M, int N, int K, const float* __restrict__ bias, int biasRows,
    const float* __restrict__ res)
{
    __shared__ float As[16][128];
    __shared__ float Bs[16][128];
    const int tid = threadIdx.x;
    const int m0 = blockIdx.x * 128;
    const int n0 = blockIdx.y * 128;
    const int tx = tid & 15, ty = tid >> 4;
    const int aRow = tid >> 2, aCol = (tid & 3) << 2;
    const int bRow = tid >> 5, bCol = (tid & 31) << 2;
    float acc[8][8];
    #pragma unroll
    for (int i = 0; i < 8; i++)
        #pragma unroll
        for (int j = 0; j < 8; j++) acc[i][j] = 0.f;

    for (int k0 = 0; k0 < K; k0 += 16) {
        #pragma unroll
        for (int h = 0; h < 2; h++) {
            int r = aRow + h * 64;
            float4 v = *reinterpret_cast<const float4*>(A + (size_t)(m0 + r) * K + (k0 + aCol));
            As[aCol+0][r] = v.x; As[aCol+1][r] = v.y; As[aCol+2][r] = v.z; As[aCol+3][r] = v.w;
        }
        #pragma unroll
        for (int h = 0; h < 2; h++) {
            int r = bRow + h * 8;
            float4 v = make_float4(0.f, 0.f, 0.f, 0.f);
            if (n0 + bCol < N)
                v = *reinterpret_cast<const float4*>(Bm + (size_t)(k0 + r) * N + (n0 + bCol));
            *reinterpret_cast<float4*>(&Bs[r][bCol]) = v;
        }
        __syncthreads();
        #pragma unroll
        for (int k = 0; k < 16; k++) {
            float4 a0 = *reinterpret_cast<const float4*>(&As[k][ty*8]);
            float4 a1 = *reinterpret_cast<const float4*>(&As[k][ty*8 + 4]);
            float4 b0 = *reinterpret_cast<const float4*>(&Bs[k][tx*8]);
            float4 b1 = *reinterpret_cast<const float4*>(&Bs[k][tx*8 + 4]);
            float av[8] = {a0.x,a0.y,a0.z,a0.w,a1.x,a1.y,a1.z,a1.w};
            float bv[8] = {b0.x,b0.y,b0.z,b0.w,b1.x,b1.y,b1.z,b1.w};
            #pragma unroll
            for (int i = 0; i < 8; i++)
                #pragma unroll
                for (int j = 0; j < 8; j++)
                    acc[i][j] += av[i] * bv[j];
        }
        __syncthreads();
    }
    #pragma unroll
    for (int i = 0; i < 8; i++) {
        int row = m0 + ty*8 + i;
        bool useB = (bias != nullptr) && (row < biasRows);
        #pragma unroll
        for (int j = 0; j < 8; j++) {
            int col = n0 + tx*8 + j;
            if (col < N) {
                float v = acc[i][j];
                if (useB) v += bias[col];
                if (res) v += res[(size_t)row * N + col];
                C[(size_t)row * N + col] = v;
            }
        }
    }
}

// ---------------- fused interp(f) * gather(x) + segment sum (primal + 3 tangents) -------------
__global__ void __launch_bounds__(128) aggK(const int* __restrict__ idx_j) {
    int i = blockIdx.x, b = blockIdx.y, t = threadIdx.x;
    const size_t TB = (size_t)BNAT * DC;
    const float invh = (float)(NQ - 1) / DMAXF;
    const float hh   = DMAXF / (float)(NQ - 1);

    __shared__ float sd[DEGC];
    __shared__ int   sj[DEGC];
    __shared__ int   sf[DEGC];
    __shared__ float sdx[DEGC], sdy[DEGC], sdz[DEGC];
    if (t < DEGC) {
        int e = i * DEGC + t;
        sd[t] = g_d[(size_t)b*EC + e];
        sj[t] = idx_j[e];
        sf[t] = g_sflag[e];
        size_t db = ((size_t)b*EC + e) * 3;
        sdx[t] = g_ddot[db + 0];
        sdy[t] = g_ddot[db + 1];
        sdz[t] = g_ddot[db + 2];
    }
    __syncthreads();

    float y = 0.f, y0 = 0.f, y1 = 0.f, y2 = 0.f;
    #pragma unroll 4
    for (int eo = 0; eo < DEGC; eo++) {
        float dv = sd[eo];
        float u = fminf(dv * invh, (float)(NQ - 1));
        int q = (int)u;
        if (q > NQ - 2) q = NQ - 2;
        float w = u - (float)q;
        float2 a0 = g_tab[(size_t)q * DC + t];
        float2 a1 = g_tab[(size_t)(q + 1) * DC + t];
        float w2 = w * w, w3 = w2 * w;
        float h00 = 2.f*w3 - 3.f*w2 + 1.f;
        float h01 = 1.f - h00;
        float h10 = w3 - 2.f*w2 + w;
        float h11 = w3 - w2;
        float fv = h00 * a0.x + h01 * a1.x + hh * (h10 * a0.y + h11 * a1.y);

        int j = sj[eo];
        size_t xb = ((size_t)b*NATC + j)*DC + t;
        float xv = g_xw4[xb];
        y  += xv * fv;
        y0 += g_xw4[TB   + xb] * fv;
        y1 += g_xw4[2*TB + xb] * fv;
        y2 += g_xw4[3*TB + xb] * fv;

        if (sf[eo]) {
            float dcom = 6.f * (w2 - w);
            float F = dcom * (a0.x - a1.x) * invh
                    + (3.f*w2 - 4.f*w + 1.f) * a0.y
                    + (3.f*w2 - 2.f*w) * a1.y;
            float xF = xv * F;
            y0 += sdx[eo] * xF;
            y1 += sdy[eo] * xF;
            y2 += sdz[eo] * xF;
        }
    }
    size_t yb = ((size_t)b*NATC + i)*DC + t;
    g_y4[yb] = y; g_y4[TB+yb] = y0; g_y4[2*TB+yb] = y1; g_y4[3*TB+yb] = y2;
}

// ---- layer-0 variant: tangent features are all zero, so only special-edge tangent terms ----
__global__ void __launch_bounds__(128) aggLightK(const int* __restrict__ idx_j) {
    int i = blockIdx.x, b = blockIdx.y, t = threadIdx.x;
    const size_t TB = (size_t)BNAT * DC;
    const float invh = (float)(NQ - 1) / DMAXF;
    const float hh   = DMAXF / (float)(NQ - 1);

    __shared__ float sd[DEGC];
    __shared__ int   sj[DEGC];
    __shared__ int   sf[DEGC];
    __shared__ float sdx[DEGC], sdy[DEGC], sdz[DEGC];
    if (t < DEGC) {
        int e = i * DEGC + t;
        sd[t] = g_d[(size_t)b*EC + e];
        sj[t] = idx_j[e];
        sf[t] = g_sflag[e];
        size_t db = ((size_t)b*EC + e) * 3;
        sdx[t] = g_ddot[db + 0];
        sdy[t] = g_ddot[db + 1];
        sdz[t] = g_ddot[db + 2];
    }
    __syncthreads();

    float y = 0.f, y0 = 0.f, y1 = 0.f, y2 = 0.f;
    #pragma unroll 4
    for (int eo = 0; eo < DEGC; eo++) {
        float dv = sd[eo];
        float u = fminf(dv * invh, (float)(NQ - 1));
        int q = (int)u;
        if (q > NQ - 2) q = NQ - 2;
        float w = u - (float)q;
        float2 a0 = g_tab[(size_t)q * DC + t];
        float2 a1 = g_tab[(size_t)(q + 1) * DC + t];
        float w2 = w * w, w3 = w2 * w;
        float h00 = 2.f*w3 - 3.f*w2 + 1.f;
        float h01 = 1.f - h00;
        float h10 = w3 - 2.f*w2 + w;
        float h11 = w3 - w2;
        float fv = h00 * a0.x + h01 * a1.x + hh * (h10 * a0.y + h11 * a1.y);

        int j = sj[eo];
        size_t xb = ((size_t)b*NATC + j)*DC + t;
        float xv = g_xw4[xb];
        y += xv * fv;

        if (sf[eo]) {
            float dcom = 6.f * (w2 - w);
            float F = dcom * (a0.x - a1.x) * invh
                    + (3.f*w2 - 4.f*w + 1.f) * a0.y
                    + (3.f*w2 - 2.f*w) * a1.y;
            float xF = xv * F;
            y0 += sdx[eo] * xF;
            y1 += sdy[eo] * xF;
            y2 += sdz[eo] * xF;
        }
    }
    size_t yb = ((size_t)b*NATC + i)*DC + t;
    g_y4[yb] = y; g_y4[TB+yb] = y0; g_y4[2*TB+yb] = y1; g_y4[3*TB+yb] = y2;
}

// ---------------- ssp on primal rows, sigmoid-mask on tangent rows (after Y4@W2) -------------
__global__ void sspTangentK() {
    int idx = blockIdx.x * blockDim.x + threadIdx.x;
    if (idx >= BNAT * DC) return;
    const size_t TB = (size_t)BNAT * DC;
    float p = g_t34[idx];
    float sg = sigf(p);
    g_t34[idx] = sspf(p);
    g_t34[TB + idx]   *= sg;
    g_t34[2*TB + idx] *= sg;
    g_t34[3*TB + idx] *= sg;
}

// ---------------- final energy tangent reduction ----------------
__global__ void energyK(const float* __restrict__ We, float* __restrict__ out) {
    int b = blockIdx.x, tid = threadIdx.x;
    const size_t TH = (size_t)BNAT * HDC;
    float a0 = 0.f, a1 = 0.f, a2 = 0.f;
    for (int idx = tid; idx < NATC * HDC; idx += 256) {
        int k = idx & (HDC - 1);
        size_t base = (size_t)b * NATC * HDC + idx;
        float p = g_h4[base];
        float w = We[k] * sigf(p);
        a0 += w * g_h4[TH   + base];
        a1 += w * g_h4[2*TH + base];
        a2 += w * g_h4[3*TH + base];
    }
    __shared__ float r0[256], r1[256], r2[256];
    r0[tid] = a0; r1[tid] = a1; r2[tid] = a2;
    __syncthreads();
    for (int s = 128; s > 0; s >>= 1) {
        if (tid < s) { r0[tid] += r0[tid+s]; r1[tid] += r1[tid+s]; r2[tid] += r2[tid+s]; }
        __syncthreads();
    }
    if (tid == 0) {
        out[b*3 + 0] = -r0[0];
        out[b*3 + 1] = -r1[0];
        out[b*3 + 2] = -r2[0];
    }
}

// ---------------- host ----------------
extern "C" void kernel_launch(void* const* d_in, const int* in_sizes, int n_in,
                              void* d_out, int out_size) {
    const float* pos     = (const float*)d_in[0];
    const int*   types   = (const int*)  d_in[1];
    const int*   idx_i   = (const int*)  d_in[2];
    const int*   idx_j   = (const int*)  d_in[3];
    /* d_in[4] = seg_i (== idx_i, unused) */
    const float* emb     = (const float*)d_in[5];
    const float* W1      = (const float*)d_in[6];
    const float* b1      = (const float*)d_in[7];
    const float* Wf1     = (const float*)d_in[8];
    const float* bf1     = (const float*)d_in[9];
    const float* Wf2     = (const float*)d_in[10];
    const float* bf2     = (const float*)d_in[11];
    const float* W2      = (const float*)d_in[12];
    const float* b2      = (const float*)d_in[13];
    const float* W3      = (const float*)d_in[14];
    const float* b3      = (const float*)d_in[15];
    const float* centers = (const float*)d_in[16];
    const float* gammaA  = (const float*)d_in[17];
    const float* Wd      = (const float*)d_in[18];
    const float* bd      = (const float*)d_in[19];
    const float* We      = (const float*)d_in[20];
    float* out = (float*)d_out;

    float *feat4, *xw4, *y4, *t34, *h4;
    cudaGetSymbolAddress((void**)&feat4, g_feat4);
    cudaGetSymbolAddress((void**)&xw4,  g_xw4);
    cudaGetSymbolAddress((void**)&y4,   g_y4);
    cudaGetSymbolAddress((void**)&t34,  g_t34);
    cudaGetSymbolAddress((void**)&h4,   g_h4);

    const int tabSmem = (RC*DC + DC*DC) * sizeof(float);   // 96 KB
    cudaFuncSetAttribute(tabK2, cudaFuncAttributeMaxDynamicSharedMemorySize, tabSmem);
    cudaFuncSetAttribute(mmaGemmK, cudaFuncAttributeMaxDynamicSharedMemorySize, MMA_SMEM);

    prepBuildK<<<EC/256, 256>>>(idx_i, idx_j);
    initK<<<(BNAT*DC)/256, 256>>>(emb, types);
    distK<<<(int)(BE/256), 256>>>(pos, idx_i, idx_j);

    for (int l = 0; l < LC; l++) {
        // x = feat @ W1 + b1 (tangents: featdot @ W1; zero at l==0 -> primal only)
        int mW1 = (l == 0) ? BNAT : M4;
        mmaGemmK<<<mW1/128, 256, MMA_SMEM>>>(feat4, W1 + (size_t)l*DC*DC, xw4,
                                             mW1, b1 + l*DC, BNAT, nullptr);
        // edge-MLP lookup table (value + derivative) for this layer
        tabK2<<<NQ/QB, DC, tabSmem>>>(Wf1, bf1, Wf2, bf2, centers, gammaA, l);
        // y = segsum(x[j]*f); ydot = segsum(xdot[j]*f + ddot*x[j]*F)
        if (l == 0) aggLightK<<<dim3(NATC, BC), 128>>>(idx_j);
        else        aggK<<<dim3(NATC, BC), 128>>>(idx_j);
        // t3 = y @ W2 + b2 (tangents raw)
        mmaGemmK<<<M4/128, 256, MMA_SMEM>>>(y4, W2 + (size_t)l*DC*DC, t34,
                                            M4, b2 + l*DC, BNAT, nullptr);
        // primal -> ssp(t3); tangents *= sigmoid(t3)
        sspTangentK<<<(BNAT*DC)/256, 256>>>();
        // feat += s3 @ W3 + b3 (tangents: featdot += s3dot @ W3)
        mmaGemmK<<<M4/128, 256, MMA_SMEM>>>(t34, W3 + (size_t)l*DC*DC, feat4,
                                            M4, b3 + l*DC, BNAT, feat4);
    }
    // pre = feat @ Wd + bd (raw); tangents: featdot @ Wd   (N=64 -> fp32 path)
    sgemmK<<<dim3(M4/128, 1), 256>>>(feat4, Wd, h4, M4, HDC, DC, bd, BNAT, nullptr);
    // out[b,0,t] = -sum We[k]*sigmoid(pre)*predot_t
    energyK<<<BC, 256>>>(We, out);
}

// round 7
// speedup vs baseline: 1.4174x; 1.0477x over previous
#include <cuda_runtime.h>
#include <cuda_bf16.h>
#include <math.h>
#include <stdint.h>

#define NATC 1024
#define DEGC 32
#define DC   128
#define RC   64
#define LC   3
#define BC   16
#define EC   (NATC*DEGC)      /* 32768 */
#define HDC  (DC/2)           /* 64 */
#define BNAT (BC*1024)        /* 16384 */
#define BE   ((size_t)BC*EC)  /* 524288 */
#define M4   (4*BNAT)         /* 65536 */
#define NQ   4096
#define QB   16
#define DMAXF 20.0f
#define LOG2C 0.69314718055994530942f

// ---------------- scratch (allocation-free: __device__ globals) ----------------
__device__ float g_feat4[(size_t)4*BNAT*DC];
__device__ float g_xw4 [(size_t)4*BNAT*DC];
__device__ float g_y4  [(size_t)4*BNAT*DC];
__device__ float g_t34 [(size_t)4*BNAT*DC];
__device__ float g_h4  [(size_t)4*BNAT*HDC];
__device__ float g_d   [BE];
__device__ float g_ddot[(size_t)BE*3];
__device__ float          g_tabF [(size_t)NQ*DC];   // f(d)
__device__ __nv_bfloat16  g_tabDh[(size_t)NQ*DC];   // hh * f'(d)  (Hermite correction only)
__device__ float          g_tabDf[(size_t)NQ*DC];   // f'(d) full precision (special edges)
__device__ int   g_sflag[EC];

// ---------------- math helpers ----------------
__device__ __forceinline__ float sspf(float x) {
    return fmaxf(x, 0.f) + log1pf(expf(-fabsf(x))) - LOG2C;
}
__device__ __forceinline__ float sigf(float x) {
    return 1.f / (1.f + expf(-x));
}

// ---------------- prep ----------------
__global__ void prepBuildK(const int* __restrict__ idx_i, const int* __restrict__ idx_j) {
    int e = blockIdx.x * blockDim.x + threadIdx.x;
    if (e >= EC) return;
    g_sflag[e] = (idx_i[e] == 0 || idx_j[e] == 0) ? 1 : 0;
}

__global__ void initK(const float* __restrict__ emb, const int* __restrict__ types) {
    int gid = blockIdx.x * blockDim.x + threadIdx.x;
    if (gid >= BNAT * DC) return;
    int bn = gid / DC;
    int d  = gid - bn * DC;
    int ty = types[bn];
    const size_t TB = (size_t)BNAT * DC;
    g_feat4[gid]        = emb[(size_t)ty * DC + d];
    g_feat4[TB + gid]   = 0.f;
    g_feat4[2*TB + gid] = 0.f;
    g_feat4[3*TB + gid] = 0.f;
}

__global__ void distK(const float* __restrict__ pos,
                      const int* __restrict__ idx_i, const int* __restrict__ idx_j) {
    int gid = blockIdx.x * blockDim.x + threadIdx.x;
    if (gid >= (int)BE) return;
    int b = gid / EC, e = gid - b * EC;
    int i = idx_i[e], j = idx_j[e];
    const float* pi = pos + ((size_t)b * NATC + i) * 3;
    const float* pj = pos + ((size_t)b * NATC + j) * 3;
    float dx = pi[0]-pj[0], dy = pi[1]-pj[1], dz = pi[2]-pj[2];
    float dv = sqrtf(dx*dx + dy*dy + dz*dz + 1e-8f);
    g_d[gid] = dv;
    float c = (float)((i == 0) - (j == 0));
    float inv = c / dv;
    g_ddot[(size_t)gid*3 + 0] = dx * inv;
    g_ddot[(size_t)gid*3 + 1] = dy * inv;
    g_ddot[(size_t)gid*3 + 2] = dz * inv;
}

// ------ per-layer edge-MLP lookup table (weights cached in dynamic smem) ------
__global__ void tabK2(const float* __restrict__ Wf1, const float* __restrict__ bf1,
                      const float* __restrict__ Wf2, const float* __restrict__ bf2,
                      const float* __restrict__ centers, const float* __restrict__ gammaA, int l) {
    extern __shared__ float sw[];
    float* w1s = sw;
    float* w2s = sw + RC*DC;
    __shared__ float rbf[RC], drb[RC], s1[DC], ds1[DC];
    int t = threadIdx.x;
    for (int idx = t; idx < RC*DC; idx += DC) w1s[idx] = Wf1[(size_t)l*RC*DC + idx];
    for (int idx = t; idx < DC*DC; idx += DC) w2s[idx] = Wf2[(size_t)l*DC*DC + idx];
    float b1v = bf1[l*DC + t];
    float b2v = bf2[l*DC + t];
    float gm = 0.f, cc = 0.f;
    if (t < RC) { gm = gammaA[l*RC + t]; cc = centers[l*RC + t]; }
    __syncthreads();

    const float hh = DMAXF / (float)(NQ - 1);
    for (int qi = 0; qi < QB; qi++) {
        int q = blockIdx.x * QB + qi;
        float dq = q * hh;
        if (t < RC) {
            float diff = dq - cc;
            float r = expf(-gm * diff * diff);
            rbf[t] = r;
            drb[t] = -2.f * gm * diff * r;
        }
        __syncthreads();
        float t1 = b1v, dt1 = 0.f;
        #pragma unroll 8
        for (int r = 0; r < RC; r++) {
            float w = w1s[r * DC + t];
            t1  += rbf[r] * w;
            dt1 += drb[r] * w;
        }
        s1[t]  = sspf(t1);
        ds1[t] = sigf(t1) * dt1;
        __syncthreads();
        float t2 = b2v, dt2 = 0.f;
        #pragma unroll 8
        for (int k = 0; k < DC; k++) {
            float w = w2s[k * DC + t];
            t2  += s1[k] * w;
            dt2 += ds1[k] * w;
        }
        float fval = sspf(t2);
        float fder = sigf(t2) * dt2;
        g_tabF [(size_t)q*DC + t] = fval;
        g_tabDh[(size_t)q*DC + t] = __float2bfloat16(hh * fder);
        g_tabDf[(size_t)q*DC + t] = fder;
        __syncthreads();
    }
}

// ---------------- mma.sync bf16 GEMM: C[M,NN] = A[M,128] @ W[128,NN] (+bias)(+res) -------
// hi/lo split: A@W ~= Ah@Wh + Al@Wh + Ah@Wl (error ~2^-16)
#define PADK 136
#define PLANEB (128 * PADK * 2)          /* bytes per 128-row bf16 plane */

__device__ __forceinline__ void mma16816(float* c, uint32_t a0, uint32_t a1, uint32_t a2, uint32_t a3,
                                         uint32_t b0, uint32_t b1) {
    asm volatile(
        "mma.sync.aligned.m16n8k16.row.col.f32.bf16.bf16.f32 "
        "{%0,%1,%2,%3}, {%4,%5,%6,%7}, {%8,%9}, {%0,%1,%2,%3};"
        : "+f"(c[0]), "+f"(c[1]), "+f"(c[2]), "+f"(c[3])
        : "r"(a0), "r"(a1), "r"(a2), "r"(a3), "r"(b0), "r"(b1));
}

__device__ __forceinline__ uint32_t pack_hi(float x0, float x1) {
    __nv_bfloat162 v; v.x = __float2bfloat16(x0); v.y = __float2bfloat16(x1);
    return *reinterpret_cast<uint32_t*>(&v);
}
__device__ __forceinline__ uint32_t pack_lo(float x0, float x1) {
    __nv_bfloat16 h0 = __float2bfloat16(x0), h1 = __float2bfloat16(x1);
    __nv_bfloat162 v;
    v.x = __float2bfloat16(x0 - __bfloat162float(h0));
    v.y = __float2bfloat16(x1 - __bfloat162float(h1));
    return *reinterpret_cast<uint32_t*>(&v);
}

template<int NN>
__global__ void __launch_bounds__(256) mmaGemmT(
    const float* __restrict__ A, const float* __restrict__ W, float* __restrict__ C,
    int M, const float* __restrict__ bias, int biasRows, const float* __restrict__ res)
{
    extern __shared__ char sm[];
    uint16_t* Ah = reinterpret_cast<uint16_t*>(sm);
    uint16_t* Al = reinterpret_cast<uint16_t*>(sm + PLANEB);
    uint16_t* Bh = reinterpret_cast<uint16_t*>(sm + 2*PLANEB);           // transposed: [n][k]
    uint16_t* Bl = reinterpret_cast<uint16_t*>(sm + 2*PLANEB + NN*PADK*2);

    const int tid = threadIdx.x;
    const int m0 = blockIdx.x * 128;

    // ---- load + split A (coalesced) ----
    {
        const float* Ab = A + (size_t)m0 * DC;
        #pragma unroll 8
        for (int it = 0; it < 32; it++) {
            int idx = it * 256 + tid;          // over 8192 float2
            int row = idx >> 6;
            int c2  = idx & 63;
            float2 x = *reinterpret_cast<const float2*>(Ab + (size_t)row * DC + c2 * 2);
            uint32_t off = row * PADK + c2 * 2;
            *reinterpret_cast<uint32_t*>(Ah + off) = pack_hi(x.x, x.y);
            *reinterpret_cast<uint32_t*>(Al + off) = pack_lo(x.x, x.y);
        }
    }
    // ---- load + split W transposed: Bt[n][k] = W[k][n] ----
    {
        int n = tid & (NN - 1);
        int kp0 = tid / NN;
        for (int kp = kp0; kp < 64; kp += 256 / NN) {
            float x0 = W[(size_t)(2*kp)     * NN + n];
            float x1 = W[(size_t)(2*kp + 1) * NN + n];
            uint32_t off = n * PADK + kp * 2;
            *reinterpret_cast<uint32_t*>(Bh + off) = pack_hi(x0, x1);
            *reinterpret_cast<uint32_t*>(Bl + off) = pack_lo(x0, x1);
        }
    }
    __syncthreads();

    const int wid = tid >> 5, lane = tid & 31;
    const int wm = wid & 3, wn = wid >> 2;     // 4 m-quadrants x 2 n-halves
    const int lr = lane >> 2, lc = lane & 3;
    constexpr int NT = NN / 16;                // n-tiles per warp-half

    float acc[2][NT][4];
    #pragma unroll
    for (int mt = 0; mt < 2; mt++)
        #pragma unroll
        for (int nt = 0; nt < NT; nt++)
            #pragma unroll
            for (int q = 0; q < 4; q++) acc[mt][nt][q] = 0.f;

    const int arow0 = wm * 32 + lr;
    const int bn0   = wn * (NN/2) + lr;

    #pragma unroll
    for (int pass = 0; pass < 3; pass++) {
        const uint16_t* Ap = (pass == 1) ? Al : Ah;
        const uint16_t* Bp = (pass == 2) ? Bl : Bh;
        #pragma unroll
        for (int ks = 0; ks < 8; ks++) {
            const int k0 = ks * 16 + lc * 2;
            uint32_t af[2][4];
            #pragma unroll
            for (int mt = 0; mt < 2; mt++) {
                const uint16_t* base = Ap + (arow0 + mt*16) * PADK + k0;
                af[mt][0] = *reinterpret_cast<const uint32_t*>(base);
                af[mt][1] = *reinterpret_cast<const uint32_t*>(base + 8 * PADK);
                af[mt][2] = *reinterpret_cast<const uint32_t*>(base + 8);
                af[mt][3] = *reinterpret_cast<const uint32_t*>(base + 8 * PADK + 8);
            }
            #pragma unroll
            for (int nt = 0; nt < NT; nt++) {
                const uint16_t* bb = Bp + (bn0 + nt*8) * PADK + k0;
                uint32_t b0 = *reinterpret_cast<const uint32_t*>(bb);
                uint32_t b1 = *reinterpret_cast<const uint32_t*>(bb + 8);
                mma16816(acc[0][nt], af[0][0], af[0][1], af[0][2], af[0][3], b0, b1);
                mma16816(acc[1][nt], af[1][0], af[1][1], af[1][2], af[1][3], b0, b1);
            }
        }
    }

    // ---- epilogue: fused bias (rows < biasRows) + residual ----
    #pragma unroll
    for (int mt = 0; mt < 2; mt++) {
        int r0 = m0 + arow0 + mt * 16;
        int r1 = r0 + 8;
        bool ub0 = (bias != nullptr) && (r0 < biasRows);
        bool ub1 = (bias != nullptr) && (r1 < biasRows);
        #pragma unroll
        for (int nt = 0; nt < NT; nt++) {
            int col = wn * (NN/2) + nt * 8 + lc * 2;
            float2 v0 = make_float2(acc[mt][nt][0], acc[mt][nt][1]);
            float2 v1 = make_float2(acc[mt][nt][2], acc[mt][nt][3]);
            if (ub0) { v0.x += bias[col]; v0.y += bias[col+1]; }
            if (ub1) { v1.x += bias[col]; v1.y += bias[col+1]; }
            if (res) {
                float2 r0v = *reinterpret_cast<const float2*>(res + (size_t)r0 * NN + col);
                float2 r1v = *reinterpret_cast<const float2*>(res + (size_t)r1 * NN + col);
                v0.x += r0v.x; v0.y += r0v.y;
                v1.x += r1v.x; v1.y += r1v.y;
            }
            *reinterpret_cast<float2*>(C + (size_t)r0 * NN + col) = v0;
            *reinterpret_cast<float2*>(C + (size_t)r1 * NN + col) = v1;
        }
    }
}

// ---------------- fused interp(f) * gather(x) + segment sum (primal + 3 tangents) -------------
__global__ void __launch_bounds__(128) aggK(const int* __restrict__ idx_j) {
    int i = blockIdx.x, b = blockIdx.y, t = threadIdx.x;
    const size_t TB = (size_t)BNAT * DC;
    const float invh = (float)(NQ - 1) / DMAXF;

    __shared__ float sd[DEGC];
    __shared__ int   sj[DEGC];
    __shared__ int   sf[DEGC];
    __shared__ float sdx[DEGC], sdy[DEGC], sdz[DEGC];
    if (t < DEGC) {
        int e = i * DEGC + t;
        sd[t] = g_d[(size_t)b*EC + e];
        sj[t] = idx_j[e];
        sf[t] = g_sflag[e];
        size_t db = ((size_t)b*EC + e) * 3;
        sdx[t] = g_ddot[db + 0];
        sdy[t] = g_ddot[db + 1];
        sdz[t] = g_ddot[db + 2];
    }
    __syncthreads();

    float y = 0.f, y0 = 0.f, y1 = 0.f, y2 = 0.f;
    #pragma unroll 4
    for (int eo = 0; eo < DEGC; eo++) {
        float dv = sd[eo];
        float u = fminf(dv * invh, (float)(NQ - 1));
        int q = (int)u;
        if (q > NQ - 2) q = NQ - 2;
        float w = u - (float)q;
        float f0 = g_tabF[(size_t)q * DC + t];
        float f1 = g_tabF[(size_t)(q + 1) * DC + t];
        float dh0 = __bfloat162float(g_tabDh[(size_t)q * DC + t]);
        float dh1 = __bfloat162float(g_tabDh[(size_t)(q + 1) * DC + t]);
        float w2 = w * w, w3 = w2 * w;
        float h00 = 2.f*w3 - 3.f*w2 + 1.f;
        float h01 = 1.f - h00;
        float h10 = w3 - 2.f*w2 + w;
        float h11 = w3 - w2;
        float fv = h00 * f0 + h01 * f1 + h10 * dh0 + h11 * dh1;

        int j = sj[eo];
        size_t xb = ((size_t)b*NATC + j)*DC + t;
        float xv = g_xw4[xb];
        y  += xv * fv;
        y0 += g_xw4[TB   + xb] * fv;
        y1 += g_xw4[2*TB + xb] * fv;
        y2 += g_xw4[3*TB + xb] * fv;

        if (sf[eo]) {
            float d0 = g_tabDf[(size_t)q * DC + t];
            float d1 = g_tabDf[(size_t)(q + 1) * DC + t];
            float dcom = 6.f * (w2 - w);
            float F = dcom * (f0 - f1) * invh
                    + (3.f*w2 - 4.f*w + 1.f) * d0
                    + (3.f*w2 - 2.f*w) * d1;
            float xF = xv * F;
            y0 += sdx[eo] * xF;
            y1 += sdy[eo] * xF;
            y2 += sdz[eo] * xF;
        }
    }
    size_t yb = ((size_t)b*NATC + i)*DC + t;
    g_y4[yb] = y; g_y4[TB+yb] = y0; g_y4[2*TB+yb] = y1; g_y4[3*TB+yb] = y2;
}

// ---- layer-0 variant: tangent features are all zero, so only special-edge tangent terms ----
__global__ void __launch_bounds__(128) aggLightK(const int* __restrict__ idx_j) {
    int i = blockIdx.x, b = blockIdx.y, t = threadIdx.x;
    const size_t TB = (size_t)BNAT * DC;
    const float invh = (float)(NQ - 1) / DMAXF;

    __shared__ float sd[DEGC];
    __shared__ int   sj[DEGC];
    __shared__ int   sf[DEGC];
    __shared__ float sdx[DEGC], sdy[DEGC], sdz[DEGC];
    if (t < DEGC) {
        int e = i * DEGC + t;
        sd[t] = g_d[(size_t)b*EC + e];
        sj[t] = idx_j[e];
        sf[t] = g_sflag[e];
        size_t db = ((size_t)b*EC + e) * 3;
        sdx[t] = g_ddot[db + 0];
        sdy[t] = g_ddot[db + 1];
        sdz[t] = g_ddot[db + 2];
    }
    __syncthreads();

    float y = 0.f, y0 = 0.f, y1 = 0.f, y2 = 0.f;
    #pragma unroll 4
    for (int eo = 0; eo < DEGC; eo++) {
        float dv = sd[eo];
        float u = fminf(dv * invh, (float)(NQ - 1));
        int q = (int)u;
        if (q > NQ - 2) q = NQ - 2;
        float w = u - (float)q;
        float f0 = g_tabF[(size_t)q * DC + t];
        float f1 = g_tabF[(size_t)(q + 1) * DC + t];
        float dh0 = __bfloat162float(g_tabDh[(size_t)q * DC + t]);
        float dh1 = __bfloat162float(g_tabDh[(size_t)(q + 1) * DC + t]);
        float w2 = w * w, w3 = w2 * w;
        float h00 = 2.f*w3 - 3.f*w2 + 1.f;
        float h01 = 1.f - h00;
        float h10 = w3 - 2.f*w2 + w;
        float h11 = w3 - w2;
        float fv = h00 * f0 + h01 * f1 + h10 * dh0 + h11 * dh1;

        int j = sj[eo];
        size_t xb = ((size_t)b*NATC + j)*DC + t;
        float xv = g_xw4[xb];
        y += xv * fv;

        if (sf[eo]) {
            float d0 = g_tabDf[(size_t)q * DC + t];
            float d1 = g_tabDf[(size_t)(q + 1) * DC + t];
            float dcom = 6.f * (w2 - w);
            float F = dcom * (f0 - f1) * invh
                    + (3.f*w2 - 4.f*w + 1.f) * d0
                    + (3.f*w2 - 2.f*w) * d1;
            float xF = xv * F;
            y0 += sdx[eo] * xF;
            y1 += sdy[eo] * xF;
            y2 += sdz[eo] * xF;
        }
    }
    size_t yb = ((size_t)b*NATC + i)*DC + t;
    g_y4[yb] = y; g_y4[TB+yb] = y0; g_y4[2*TB+yb] = y1; g_y4[3*TB+yb] = y2;
}

// ---------------- ssp on primal rows, sigmoid-mask on tangent rows (after Y4@W2) -------------
__global__ void sspTangentK() {
    int idx = blockIdx.x * blockDim.x + threadIdx.x;
    if (idx >= BNAT * DC) return;
    const size_t TB = (size_t)BNAT * DC;
    float p = g_t34[idx];
    float sg = sigf(p);
    g_t34[idx] = sspf(p);
    g_t34[TB + idx]   *= sg;
    g_t34[2*TB + idx] *= sg;
    g_t34[3*TB + idx] *= sg;
}

// ---------------- final energy tangent reduction ----------------
__global__ void energyK(const float* __restrict__ We, float* __restrict__ out) {
    int b = blockIdx.x, tid = threadIdx.x;
    const size_t TH = (size_t)BNAT * HDC;
    float a0 = 0.f, a1 = 0.f, a2 = 0.f;
    for (int idx = tid; idx < NATC * HDC; idx += 256) {
        int k = idx & (HDC - 1);
        size_t base = (size_t)b * NATC * HDC + idx;
        float p = g_h4[base];
        float w = We[k] * sigf(p);
        a0 += w * g_h4[TH   + base];
        a1 += w * g_h4[2*TH + base];
        a2 += w * g_h4[3*TH + base];
    }
    __shared__ float r0[256], r1[256], r2[256];
    r0[tid] = a0; r1[tid] = a1; r2[tid] = a2;
    __syncthreads();
    for (int s = 128; s > 0; s >>= 1) {
        if (tid < s) { r0[tid] += r0[tid+s]; r1[tid] += r1[tid+s]; r2[tid] += r2[tid+s]; }
        __syncthreads();
    }
    if (tid == 0) {
        out[b*3 + 0] = -r0[0];
        out[b*3 + 1] = -r1[0];
        out[b*3 + 2] = -r2[0];
    }
}

// ---------------- host ----------------
extern "C" void kernel_launch(void* const* d_in, const int* in_sizes, int n_in,
                              void* d_out, int out_size) {
    const float* pos     = (const float*)d_in[0];
    const int*   types   = (const int*)  d_in[1];
    const int*   idx_i   = (const int*)  d_in[2];
    const int*   idx_j   = (const int*)  d_in[3];
    /* d_in[4] = seg_i (== idx_i, unused) */
    const float* emb     = (const float*)d_in[5];
    const float* W1      = (const float*)d_in[6];
    const float* b1      = (const float*)d_in[7];
    const float* Wf1     = (const float*)d_in[8];
    const float* bf1     = (const float*)d_in[9];
    const float* Wf2     = (const float*)d_in[10];
    const float* bf2     = (const float*)d_in[11];
    const float* W2      = (const float*)d_in[12];
    const float* b2      = (const float*)d_in[13];
    const float* W3      = (const float*)d_in[14];
    const float* b3      = (const float*)d_in[15];
    const float* centers = (const float*)d_in[16];
    const float* gammaA  = (const float*)d_in[17];
    const float* Wd      = (const float*)d_in[18];
    const float* bd      = (const float*)d_in[19];
    const float* We      = (const float*)d_in[20];
    float* out = (float*)d_out;

    float *feat4, *xw4, *y4, *t34, *h4;
    cudaGetSymbolAddress((void**)&feat4, g_feat4);
    cudaGetSymbolAddress((void**)&xw4,  g_xw4);
    cudaGetSymbolAddress((void**)&y4,   g_y4);
    cudaGetSymbolAddress((void**)&t34,  g_t34);
    cudaGetSymbolAddress((void**)&h4,   g_h4);

    const int tabSmem = (RC*DC + DC*DC) * sizeof(float);               // 96 KB
    const int smem128 = 2*PLANEB + 2*128*PADK*2;                       // 136 KB
    const int smem64  = 2*PLANEB + 2*64*PADK*2;                        // 102 KB
    cudaFuncSetAttribute(tabK2, cudaFuncAttributeMaxDynamicSharedMemorySize, tabSmem);
    cudaFuncSetAttribute(mmaGemmT<128>, cudaFuncAttributeMaxDynamicSharedMemorySize, smem128);
    cudaFuncSetAttribute(mmaGemmT<64>,  cudaFuncAttributeMaxDynamicSharedMemorySize, smem64);

    prepBuildK<<<EC/256, 256>>>(idx_i, idx_j);
    initK<<<(BNAT*DC)/256, 256>>>(emb, types);
    distK<<<(int)(BE/256), 256>>>(pos, idx_i, idx_j);

    for (int l = 0; l < LC; l++) {
        // x = feat @ W1 + b1 (tangents: featdot @ W1; zero at l==0 -> primal only)
        int mW1 = (l == 0) ? BNAT : M4;
        mmaGemmT<128><<<mW1/128, 256, smem128>>>(feat4, W1 + (size_t)l*DC*DC, xw4,
                                                 mW1, b1 + l*DC, BNAT, nullptr);
        // edge-MLP lookup table (value + derivative) for this layer
        tabK2<<<NQ/QB, DC, tabSmem>>>(Wf1, bf1, Wf2, bf2, centers, gammaA, l);
        // y = segsum(x[j]*f); ydot = segsum(xdot[j]*f + ddot*x[j]*F)
        if (l == 0) aggLightK<<<dim3(NATC, BC), 128>>>(idx_j);
        else        aggK<<<dim3(NATC, BC), 128>>>(idx_j);
        // t3 = y @ W2 + b2 (tangents raw)
        mmaGemmT<128><<<M4/128, 256, smem128>>>(y4, W2 + (size_t)l*DC*DC, t34,
                                                M4, b2 + l*DC, BNAT, nullptr);
        // primal -> ssp(t3); tangents *= sigmoid(t3)
        sspTangentK<<<(BNAT*DC)/256, 256>>>();
        // feat += s3 @ W3 + b3 (tangents: featdot += s3dot @ W3)
        mmaGemmT<128><<<M4/128, 256, smem128>>>(t34, W3 + (size_t)l*DC*DC, feat4,
                                                M4, b3 + l*DC, BNAT, feat4);
    }
    // pre = feat @ Wd + bd (raw); tangents: featdot @ Wd   (N=64 HMMA)
    mmaGemmT<64><<<M4/128, 256, smem64>>>(feat4, Wd, h4, M4, bd, BNAT, nullptr);
    // out[b,0,t] = -sum We[k]*sigmoid(pre)*predot_t
    energyK<<<BC, 256>>>(We, out);
}

// round 8
// speedup vs baseline: 1.6686x; 1.1773x over previous
#include <cuda_runtime.h>
#include <cuda_bf16.h>
#include <math.h>
#include <stdint.h>

#define NATC 1024
#define DEGC 32
#define DC   128
#define RC   64
#define LC   3
#define BC   16
#define EC   (NATC*DEGC)      /* 32768 */
#define HDC  (DC/2)           /* 64 */
#define BNAT (BC*1024)        /* 16384 */
#define BE   ((size_t)BC*EC)  /* 524288 */
#define M4   (4*BNAT)         /* 65536 */
#define NQ   1024
#define QB   16
#define DMAXF 20.0f
#define LOG2C 0.69314718055994530942f

// ---------------- scratch (allocation-free: __device__ globals) ----------------
__device__ float g_feat4[(size_t)4*BNAT*DC];
__device__ float g_xw4 [(size_t)4*BNAT*DC];
__device__ float g_y4  [(size_t)4*BNAT*DC];
__device__ float g_t34 [(size_t)4*BNAT*DC];
__device__ float g_h4  [(size_t)4*BNAT*HDC];
__device__ float g_d   [BE];
__device__ float g_ddot[(size_t)BE*3];
__device__ float          g_tabF [(size_t)NQ*DC];   // f(d)
__device__ __nv_bfloat16  g_tabDh[(size_t)NQ*DC];   // hh * f'(d)  (Hermite correction)
__device__ float          g_tabDf[(size_t)NQ*DC];   // f'(d) full precision (special edges)
__device__ int   g_sflag[EC];

// ---------------- math helpers ----------------
__device__ __forceinline__ float sspf(float x) {
    return fmaxf(x, 0.f) + log1pf(expf(-fabsf(x))) - LOG2C;
}
__device__ __forceinline__ float sigf(float x) {
    return 1.f / (1.f + expf(-x));
}

// ---------------- prep ----------------
__global__ void prepBuildK(const int* __restrict__ idx_i, const int* __restrict__ idx_j) {
    int e = blockIdx.x * blockDim.x + threadIdx.x;
    if (e >= EC) return;
    g_sflag[e] = (idx_i[e] == 0 || idx_j[e] == 0) ? 1 : 0;
}

__global__ void initK(const float* __restrict__ emb, const int* __restrict__ types) {
    int gid = blockIdx.x * blockDim.x + threadIdx.x;
    if (gid >= BNAT * DC) return;
    int bn = gid / DC;
    int d  = gid - bn * DC;
    int ty = types[bn];
    const size_t TB = (size_t)BNAT * DC;
    g_feat4[gid]        = emb[(size_t)ty * DC + d];
    g_feat4[TB + gid]   = 0.f;
    g_feat4[2*TB + gid] = 0.f;
    g_feat4[3*TB + gid] = 0.f;
}

__global__ void distK(const float* __restrict__ pos,
                      const int* __restrict__ idx_i, const int* __restrict__ idx_j) {
    int gid = blockIdx.x * blockDim.x + threadIdx.x;
    if (gid >= (int)BE) return;
    int b = gid / EC, e = gid - b * EC;
    int i = idx_i[e], j = idx_j[e];
    const float* pi = pos + ((size_t)b * NATC + i) * 3;
    const float* pj = pos + ((size_t)b * NATC + j) * 3;
    float dx = pi[0]-pj[0], dy = pi[1]-pj[1], dz = pi[2]-pj[2];
    float dv = sqrtf(dx*dx + dy*dy + dz*dz + 1e-8f);
    g_d[gid] = dv;
    float c = (float)((i == 0) - (j == 0));
    float inv = c / dv;
    g_ddot[(size_t)gid*3 + 0] = dx * inv;
    g_ddot[(size_t)gid*3 + 1] = dy * inv;
    g_ddot[(size_t)gid*3 + 2] = dz * inv;
}

// ------ per-layer edge-MLP lookup table (weights cached in dynamic smem) ------
__global__ void tabK2(const float* __restrict__ Wf1, const float* __restrict__ bf1,
                      const float* __restrict__ Wf2, const float* __restrict__ bf2,
                      const float* __restrict__ centers, const float* __restrict__ gammaA, int l) {
    extern __shared__ float sw[];
    float* w1s = sw;
    float* w2s = sw + RC*DC;
    __shared__ float rbf[RC], drb[RC], s1[DC], ds1[DC];
    int t = threadIdx.x;
    for (int idx = t; idx < RC*DC; idx += DC) w1s[idx] = Wf1[(size_t)l*RC*DC + idx];
    for (int idx = t; idx < DC*DC; idx += DC) w2s[idx] = Wf2[(size_t)l*DC*DC + idx];
    float b1v = bf1[l*DC + t];
    float b2v = bf2[l*DC + t];
    float gm = 0.f, cc = 0.f;
    if (t < RC) { gm = gammaA[l*RC + t]; cc = centers[l*RC + t]; }
    __syncthreads();

    const float hh = DMAXF / (float)(NQ - 1);
    for (int qi = 0; qi < QB; qi++) {
        int q = blockIdx.x * QB + qi;
        float dq = q * hh;
        if (t < RC) {
            float diff = dq - cc;
            float r = expf(-gm * diff * diff);
            rbf[t] = r;
            drb[t] = -2.f * gm * diff * r;
        }
        __syncthreads();
        float t1 = b1v, dt1 = 0.f;
        #pragma unroll 8
        for (int r = 0; r < RC; r++) {
            float w = w1s[r * DC + t];
            t1  += rbf[r] * w;
            dt1 += drb[r] * w;
        }
        s1[t]  = sspf(t1);
        ds1[t] = sigf(t1) * dt1;
        __syncthreads();
        float t2 = b2v, dt2 = 0.f;
        #pragma unroll 8
        for (int k = 0; k < DC; k++) {
            float w = w2s[k * DC + t];
            t2  += s1[k] * w;
            dt2 += ds1[k] * w;
        }
        float fval = sspf(t2);
        float fder = sigf(t2) * dt2;
        g_tabF [(size_t)q*DC + t] = fval;
        g_tabDh[(size_t)q*DC + t] = __float2bfloat16(hh * fder);
        g_tabDf[(size_t)q*DC + t] = fder;
        __syncthreads();
    }
}

// ---------------- mma.sync bf16 GEMM: C[M,NN] = A[M,128] @ W[128,NN] (+bias)(+res) -------
#define PADK 136
#define PLANEB (128 * PADK * 2)

__device__ __forceinline__ void mma16816(float* c, uint32_t a0, uint32_t a1, uint32_t a2, uint32_t a3,
                                         uint32_t b0, uint32_t b1) {
    asm volatile(
        "mma.sync.aligned.m16n8k16.row.col.f32.bf16.bf16.f32 "
        "{%0,%1,%2,%3}, {%4,%5,%6,%7}, {%8,%9}, {%0,%1,%2,%3};"
        : "+f"(c[0]), "+f"(c[1]), "+f"(c[2]), "+f"(c[3])
        : "r"(a0), "r"(a1), "r"(a2), "r"(a3), "r"(b0), "r"(b1));
}

__device__ __forceinline__ uint32_t pack_hi(float x0, float x1) {
    __nv_bfloat162 v; v.x = __float2bfloat16(x0); v.y = __float2bfloat16(x1);
    return *reinterpret_cast<uint32_t*>(&v);
}
__device__ __forceinline__ uint32_t pack_lo(float x0, float x1) {
    __nv_bfloat16 h0 = __float2bfloat16(x0), h1 = __float2bfloat16(x1);
    __nv_bfloat162 v;
    v.x = __float2bfloat16(x0 - __bfloat162float(h0));
    v.y = __float2bfloat16(x1 - __bfloat162float(h1));
    return *reinterpret_cast<uint32_t*>(&v);
}

template<int NN>
__global__ void __launch_bounds__(256) mmaGemmT(
    const float* __restrict__ A, const float* __restrict__ W, float* __restrict__ C,
    int M, const float* __restrict__ bias, int biasRows, const float* __restrict__ res)
{
    extern __shared__ char sm[];
    uint16_t* Ah = reinterpret_cast<uint16_t*>(sm);
    uint16_t* Al = reinterpret_cast<uint16_t*>(sm + PLANEB);
    uint16_t* Bh = reinterpret_cast<uint16_t*>(sm + 2*PLANEB);
    uint16_t* Bl = reinterpret_cast<uint16_t*>(sm + 2*PLANEB + NN*PADK*2);

    const int tid = threadIdx.x;
    const int m0 = blockIdx.x * 128;

    {
        const float* Ab = A + (size_t)m0 * DC;
        #pragma unroll 8
        for (int it = 0; it < 32; it++) {
            int idx = it * 256 + tid;
            int row = idx >> 6;
            int c2  = idx & 63;
            float2 x = *reinterpret_cast<const float2*>(Ab + (size_t)row * DC + c2 * 2);
            uint32_t off = row * PADK + c2 * 2;
            *reinterpret_cast<uint32_t*>(Ah + off) = pack_hi(x.x, x.y);
            *reinterpret_cast<uint32_t*>(Al + off) = pack_lo(x.x, x.y);
        }
    }
    {
        int n = tid & (NN - 1);
        int kp0 = tid / NN;
        for (int kp = kp0; kp < 64; kp += 256 / NN) {
            float x0 = W[(size_t)(2*kp)     * NN + n];
            float x1 = W[(size_t)(2*kp + 1) * NN + n];
            uint32_t off = n * PADK + kp * 2;
            *reinterpret_cast<uint32_t*>(Bh + off) = pack_hi(x0, x1);
            *reinterpret_cast<uint32_t*>(Bl + off) = pack_lo(x0, x1);
        }
    }
    __syncthreads();

    const int wid = tid >> 5, lane = tid & 31;
    const int wm = wid & 3, wn = wid >> 2;
    const int lr = lane >> 2, lc = lane & 3;
    constexpr int NT = NN / 16;

    float acc[2][NT][4];
    #pragma unroll
    for (int mt = 0; mt < 2; mt++)
        #pragma unroll
        for (int nt = 0; nt < NT; nt++)
            #pragma unroll
            for (int q = 0; q < 4; q++) acc[mt][nt][q] = 0.f;

    const int arow0 = wm * 32 + lr;
    const int bn0   = wn * (NN/2) + lr;

    #pragma unroll
    for (int pass = 0; pass < 3; pass++) {
        const uint16_t* Ap = (pass == 1) ? Al : Ah;
        const uint16_t* Bp = (pass == 2) ? Bl : Bh;
        #pragma unroll
        for (int ks = 0; ks < 8; ks++) {
            const int k0 = ks * 16 + lc * 2;
            uint32_t af[2][4];
            #pragma unroll
            for (int mt = 0; mt < 2; mt++) {
                const uint16_t* base = Ap + (arow0 + mt*16) * PADK + k0;
                af[mt][0] = *reinterpret_cast<const uint32_t*>(base);
                af[mt][1] = *reinterpret_cast<const uint32_t*>(base + 8 * PADK);
                af[mt][2] = *reinterpret_cast<const uint32_t*>(base + 8);
                af[mt][3] = *reinterpret_cast<const uint32_t*>(base + 8 * PADK + 8);
            }
            #pragma unroll
            for (int nt = 0; nt < NT; nt++) {
                const uint16_t* bb = Bp + (bn0 + nt*8) * PADK + k0;
                uint32_t b0 = *reinterpret_cast<const uint32_t*>(bb);
                uint32_t b1 = *reinterpret_cast<const uint32_t*>(bb + 8);
                mma16816(acc[0][nt], af[0][0], af[0][1], af[0][2], af[0][3], b0, b1);
                mma16816(acc[1][nt], af[1][0], af[1][1], af[1][2], af[1][3], b0, b1);
            }
        }
    }

    #pragma unroll
    for (int mt = 0; mt < 2; mt++) {
        int r0 = m0 + arow0 + mt * 16;
        int r1 = r0 + 8;
        bool ub0 = (bias != nullptr) && (r0 < biasRows);
        bool ub1 = (bias != nullptr) && (r1 < biasRows);
        #pragma unroll
        for (int nt = 0; nt < NT; nt++) {
            int col = wn * (NN/2) + nt * 8 + lc * 2;
            float2 v0 = make_float2(acc[mt][nt][0], acc[mt][nt][1]);
            float2 v1 = make_float2(acc[mt][nt][2], acc[mt][nt][3]);
            if (ub0) { v0.x += bias[col]; v0.y += bias[col+1]; }
            if (ub1) { v1.x += bias[col]; v1.y += bias[col+1]; }
            if (res) {
                float2 r0v = *reinterpret_cast<const float2*>(res + (size_t)r0 * NN + col);
                float2 r1v = *reinterpret_cast<const float2*>(res + (size_t)r1 * NN + col);
                v0.x += r0v.x; v0.y += r0v.y;
                v1.x += r1v.x; v1.y += r1v.y;
            }
            *reinterpret_cast<float2*>(C + (size_t)r0 * NN + col) = v0;
            *reinterpret_cast<float2*>(C + (size_t)r1 * NN + col) = v1;
        }
    }
}

// -------- vectorized agg: warp = atom, lane = 4 cols; LDG.128 everywhere --------
template<bool LIGHT>
__global__ void __launch_bounds__(128) aggV(const int* __restrict__ idx_j) {
    const int b = blockIdx.y;
    const int warp = threadIdx.x >> 5, lane = threadIdx.x & 31;
    const int i = blockIdx.x * 4 + warp;
    const size_t TBq = ((size_t)BNAT * DC) >> 2;      // float4 units
    const float invh = (float)(NQ - 1) / DMAXF;

    __shared__ float sd[128], sdx[128], sdy[128], sdz[128];
    __shared__ int sj[128], sf[128];
    {
        int tid = threadIdx.x;
        int e = blockIdx.x * 128 + tid;
        sd[tid] = g_d[(size_t)b*EC + e];
        sj[tid] = idx_j[e];
        sf[tid] = g_sflag[e];
        size_t db = ((size_t)b*EC + e) * 3;
        sdx[tid] = g_ddot[db + 0];
        sdy[tid] = g_ddot[db + 1];
        sdz[tid] = g_ddot[db + 2];
    }
    __syncthreads();

    const float4* xp = reinterpret_cast<const float4*>(g_xw4);
    const float4* tF = reinterpret_cast<const float4*>(g_tabF);
    const float4* tD = reinterpret_cast<const float4*>(g_tabDf);
    const uint2*  tH = reinterpret_cast<const uint2*>(g_tabDh);

    float4 y  = make_float4(0.f,0.f,0.f,0.f);
    float4 ya = y, yb_ = y, yc = y;
    const int e0 = warp * 32;

    #pragma unroll 4
    for (int eo = 0; eo < DEGC; eo++) {
        int ee = e0 + eo;
        float dv = sd[ee];
        float u = fminf(dv * invh, (float)(NQ - 1));
        int q = (int)u;
        if (q > NQ - 2) q = NQ - 2;
        float w = u - (float)q;
        float w2 = w*w, w3 = w2*w;
        float h00 = 2.f*w3 - 3.f*w2 + 1.f;
        float h01 = 1.f - h00;
        float h10 = w3 - 2.f*w2 + w;
        float h11 = w3 - w2;

        int ti0 = q * 32 + lane, ti1 = ti0 + 32;
        float4 f0 = tF[ti0], f1 = tF[ti1];
        uint2 hu0 = tH[ti0], hu1 = tH[ti1];
        float2 d0lo = __bfloat1622float2(*reinterpret_cast<const __nv_bfloat162*>(&hu0.x));
        float2 d0hi = __bfloat1622float2(*reinterpret_cast<const __nv_bfloat162*>(&hu0.y));
        float2 d1lo = __bfloat1622float2(*reinterpret_cast<const __nv_bfloat162*>(&hu1.x));
        float2 d1hi = __bfloat1622float2(*reinterpret_cast<const __nv_bfloat162*>(&hu1.y));

        float4 fv;
        fv.x = h00*f0.x + h01*f1.x + h10*d0lo.x + h11*d1lo.x;
        fv.y = h00*f0.y + h01*f1.y + h10*d0lo.y + h11*d1lo.y;
        fv.z = h00*f0.z + h01*f1.z + h10*d0hi.x + h11*d1hi.x;
        fv.w = h00*f0.w + h01*f1.w + h10*d0hi.y + h11*d1hi.y;

        int j = sj[ee];
        size_t xb = (((size_t)b*NATC + j) << 5) + lane;   // *DC/4 = *32
        float4 xv = xp[xb];
        y.x += xv.x*fv.x; y.y += xv.y*fv.y; y.z += xv.z*fv.z; y.w += xv.w*fv.w;
        if (!LIGHT) {
            float4 x0 = xp[TBq + xb];
            float4 x1 = xp[2*TBq + xb];
            float4 x2 = xp[3*TBq + xb];
            ya.x += x0.x*fv.x; ya.y += x0.y*fv.y; ya.z += x0.z*fv.z; ya.w += x0.w*fv.w;
            yb_.x += x1.x*fv.x; yb_.y += x1.y*fv.y; yb_.z += x1.z*fv.z; yb_.w += x1.w*fv.w;
            yc.x += x2.x*fv.x; yc.y += x2.y*fv.y; yc.z += x2.z*fv.z; yc.w += x2.w*fv.w;
        }

        if (sf[ee]) {
            float4 g0 = tD[ti0], g1 = tD[ti1];
            float dcom = 6.f * (w2 - w) * invh;
            float c0 = 3.f*w2 - 4.f*w + 1.f;
            float c1 = 3.f*w2 - 2.f*w;
            float4 F;
            F.x = dcom*(f0.x - f1.x) + c0*g0.x + c1*g1.x;
            F.y = dcom*(f0.y - f1.y) + c0*g0.y + c1*g1.y;
            F.z = dcom*(f0.z - f1.z) + c0*g0.z + c1*g1.z;
            F.w = dcom*(f0.w - f1.w) + c0*g0.w + c1*g1.w;
            float ax = sdx[ee], ay = sdy[ee], az = sdz[ee];
            float4 xF;
            xF.x = xv.x*F.x; xF.y = xv.y*F.y; xF.z = xv.z*F.z; xF.w = xv.w*F.w;
            ya.x += ax*xF.x; ya.y += ax*xF.y; ya.z += ax*xF.z; ya.w += ax*xF.w;
            yb_.x += ay*xF.x; yb_.y += ay*xF.y; yb_.z += ay*xF.z; yb_.w += ay*xF.w;
            yc.x += az*xF.x; yc.y += az*xF.y; yc.z += az*xF.z; yc.w += az*xF.w;
        }
    }

    float4* yp = reinterpret_cast<float4*>(g_y4);
    size_t yo = (((size_t)b*NATC + i) << 5) + lane;
    yp[yo] = y;
    yp[TBq + yo] = ya;
    yp[2*TBq + yo] = yb_;
    yp[3*TBq + yo] = yc;
}

// ---------------- ssp on primal rows, sigmoid-mask on tangent rows (after Y4@W2) -------------
__global__ void sspTangentK() {
    int idx = blockIdx.x * blockDim.x + threadIdx.x;
    if (idx >= BNAT * DC) return;
    const size_t TB = (size_t)BNAT * DC;
    float p = g_t34[idx];
    float sg = sigf(p);
    g_t34[idx] = sspf(p);
    g_t34[TB + idx]   *= sg;
    g_t34[2*TB + idx] *= sg;
    g_t34[3*TB + idx] *= sg;
}

// ---------------- final energy tangent reduction ----------------
__global__ void energyK(const float* __restrict__ We, float* __restrict__ out) {
    int b = blockIdx.x, tid = threadIdx.x;
    const size_t TH = (size_t)BNAT * HDC;
    float a0 = 0.f, a1 = 0.f, a2 = 0.f;
    for (int idx = tid; idx < NATC * HDC; idx += 256) {
        int k = idx & (HDC - 1);
        size_t base = (size_t)b * NATC * HDC + idx;
        float p = g_h4[base];
        float w = We[k] * sigf(p);
        a0 += w * g_h4[TH   + base];
        a1 += w * g_h4[2*TH + base];
        a2 += w * g_h4[3*TH + base];
    }
    __shared__ float r0[256], r1[256], r2[256];
    r0[tid] = a0; r1[tid] = a1; r2[tid] = a2;
    __syncthreads();
    for (int s = 128; s > 0; s >>= 1) {
        if (tid < s) { r0[tid] += r0[tid+s]; r1[tid] += r1[tid+s]; r2[tid] += r2[tid+s]; }
        __syncthreads();
    }
    if (tid == 0) {
        out[b*3 + 0] = -r0[0];
        out[b*3 + 1] = -r1[0];
        out[b*3 + 2] = -r2[0];
    }
}

// ---------------- host ----------------
extern "C" void kernel_launch(void* const* d_in, const int* in_sizes, int n_in,
                              void* d_out, int out_size) {
    const float* pos     = (const float*)d_in[0];
    const int*   types   = (const int*)  d_in[1];
    const int*   idx_i   = (const int*)  d_in[2];
    const int*   idx_j   = (const int*)  d_in[3];
    /* d_in[4] = seg_i (== idx_i, unused) */
    const float* emb     = (const float*)d_in[5];
    const float* W1      = (const float*)d_in[6];
    const float* b1      = (const float*)d_in[7];
    const float* Wf1     = (const float*)d_in[8];
    const float* bf1     = (const float*)d_in[9];
    const float* Wf2     = (const float*)d_in[10];
    const float* bf2     = (const float*)d_in[11];
    const float* W2      = (const float*)d_in[12];
    const float* b2      = (const float*)d_in[13];
    const float* W3      = (const float*)d_in[14];
    const float* b3      = (const float*)d_in[15];
    const float* centers = (const float*)d_in[16];
    const float* gammaA  = (const float*)d_in[17];
    const float* Wd      = (const float*)d_in[18];
    const float* bd      = (const float*)d_in[19];
    const float* We      = (const float*)d_in[20];
    float* out = (float*)d_out;

    float *feat4, *xw4, *y4, *t34, *h4;
    cudaGetSymbolAddress((void**)&feat4, g_feat4);
    cudaGetSymbolAddress((void**)&xw4,  g_xw4);
    cudaGetSymbolAddress((void**)&y4,   g_y4);
    cudaGetSymbolAddress((void**)&t34,  g_t34);
    cudaGetSymbolAddress((void**)&h4,   g_h4);

    const int tabSmem = (RC*DC + DC*DC) * sizeof(float);               // 96 KB
    const int smem128 = 2*PLANEB + 2*128*PADK*2;                       // 136 KB
    const int smem64  = 2*PLANEB + 2*64*PADK*2;                        // 102 KB
    cudaFuncSetAttribute(tabK2, cudaFuncAttributeMaxDynamicSharedMemorySize, tabSmem);
    cudaFuncSetAttribute(mmaGemmT<128>, cudaFuncAttributeMaxDynamicSharedMemorySize, smem128);
    cudaFuncSetAttribute(mmaGemmT<64>,  cudaFuncAttributeMaxDynamicSharedMemorySize, smem64);

    prepBuildK<<<EC/256, 256>>>(idx_i, idx_j);
    initK<<<(BNAT*DC)/256, 256>>>(emb, types);
    distK<<<(int)(BE/256), 256>>>(pos, idx_i, idx_j);

    for (int l = 0; l < LC; l++) {
        int mW1 = (l == 0) ? BNAT : M4;
        mmaGemmT<128><<<mW1/128, 256, smem128>>>(feat4, W1 + (size_t)l*DC*DC, xw4,
                                                 mW1, b1 + l*DC, BNAT, nullptr);
        tabK2<<<NQ/QB, DC, tabSmem>>>(Wf1, bf1, Wf2, bf2, centers, gammaA, l);
        if (l == 0) aggV<true><<<dim3(NATC/4, BC), 128>>>(idx_j);
        else        aggV<false><<<dim3(NATC/4, BC), 128>>>(idx_j);
        mmaGemmT<128><<<M4/128, 256, smem128>>>(y4, W2 + (size_t)l*DC*DC, t34,
                                                M4, b2 + l*DC, BNAT, nullptr);
        sspTangentK<<<(BNAT*DC)/256, 256>>>();
        mmaGemmT<128><<<M4/128, 256, smem128>>>(t34, W3 + (size_t)l*DC*DC, feat4,
                                                M4, b3 + l*DC, BNAT, feat4);
    }
    mmaGemmT<64><<<M4/128, 256, smem64>>>(feat4, Wd, h4, M4, bd, BNAT, nullptr);
    energyK<<<BC, 256>>>(We, out);
}